// round 15
// baseline (speedup 1.0000x reference)
#include <cuda_runtime.h>
#include <cuda_fp16.h>
#include <cstdint>

#define NN 100000
#define EE 1600000
#define DD 128
#define LL 3
#define GG 512
#define NSM 148

// ---------------- scratch (device globals; no allocation allowed) ----------------
__device__ __half g_hx[NN * DD];        // h (and x): agg gather source / layer output
__device__ __half g_af[NN * DD];        // agg output (layer GEMM A operand)
__device__ __half g_wh[7 * DD * DD];    // weights hi (fp16), transposed [n][k]
__device__ __half g_wl[DD * DD];        // lin weight lo residual only
__device__ __half g_pf[GG * DD];        // pooled (fp16)
__device__ int   g_deg[NN];
__device__ int   g_rowptr[NN + 1];
__device__ int   g_cursor[NN];
__device__ int   g_colidx[EE];
__device__ int   g_bsums[512];
__device__ int   g_gcnt[GG];
__device__ int   g_goff[GG + 1];

// ---------------- PTX helpers ----------------
__device__ __forceinline__ uint32_t smem_u32(const void* p) {
    uint32_t a;
    asm("{ .reg .u64 t; cvta.to.shared.u64 t, %1; cvt.u32.u64 %0, t; }" : "=r"(a) : "l"(p));
    return a;
}
__device__ __forceinline__ void ldsm_x4(uint32_t* r, uint32_t addr) {
    asm volatile("ldmatrix.sync.aligned.m8n8.x4.shared.b16 {%0,%1,%2,%3}, [%4];"
        : "=r"(r[0]), "=r"(r[1]), "=r"(r[2]), "=r"(r[3]) : "r"(addr));
}
__device__ __forceinline__ void mma16816h(float* c, const uint32_t* a, const uint32_t* b) {
    asm volatile("mma.sync.aligned.m16n8k16.row.col.f32.f16.f16.f32 "
        "{%0,%1,%2,%3}, {%4,%5,%6,%7}, {%8,%9}, {%0,%1,%2,%3};"
        : "+f"(c[0]), "+f"(c[1]), "+f"(c[2]), "+f"(c[3])
        : "r"(a[0]), "r"(a[1]), "r"(a[2]), "r"(a[3]), "r"(b[0]), "r"(b[1]));
}
__device__ __forceinline__ void cp_async16(uint32_t smem_addr, const void* gptr, int src_bytes) {
    asm volatile("cp.async.cg.shared.global [%0], [%1], 16, %2;"
        :: "r"(smem_addr), "l"(gptr), "r"(src_bytes) : "memory");
}
#define CP_COMMIT() asm volatile("cp.async.commit_group;" ::: "memory")
#define CP_WAIT1()  asm volatile("cp.async.wait_group 1;" ::: "memory")

// ---------------- CSR + pool-offset build (vectorized) ----------------
__global__ void k_counts(const int* __restrict__ dst, const int* __restrict__ batch) {
    int i = blockIdx.x * blockDim.x + threadIdx.x;
    if (i < EE / 4) {
        int4 d = ((const int4*)dst)[i];
        atomicAdd(&g_deg[d.x], 1);
        atomicAdd(&g_deg[d.y], 1);
        atomicAdd(&g_deg[d.z], 1);
        atomicAdd(&g_deg[d.w], 1);
    }
    if (i < NN / 4) {
        int4 b = ((const int4*)batch)[i];
        atomicAdd(&g_gcnt[b.x], 1);
        atomicAdd(&g_gcnt[b.y], 1);
        atomicAdd(&g_gcnt[b.z], 1);
        atomicAdd(&g_gcnt[b.w], 1);
    }
}
#define SCAN_B 512
__global__ void k_scan1() {
    __shared__ int tmp[SCAN_B];
    int t = threadIdx.x;
    int g = blockIdx.x * SCAN_B + t;
    int v = (g < NN) ? g_deg[g] : 0;
    tmp[t] = v;
    __syncthreads();
    for (int off = 1; off < SCAN_B; off <<= 1) {
        int add = (t >= off) ? tmp[t - off] : 0;
        __syncthreads();
        tmp[t] += add;
        __syncthreads();
    }
    if (g < NN) g_rowptr[g] = tmp[t] - v;
    if (t == SCAN_B - 1) g_bsums[blockIdx.x] = tmp[t];
}
__global__ void k_scan2g(int nb) {
    __shared__ int tmp[512];
    int t = threadIdx.x;
    if (blockIdx.x == 0) {
        int v = (t < nb) ? g_bsums[t] : 0;
        tmp[t] = v;
        __syncthreads();
        for (int off = 1; off < 512; off <<= 1) {
            int add = (t >= off) ? tmp[t - off] : 0;
            __syncthreads();
            tmp[t] += add;
            __syncthreads();
        }
        if (t < nb) g_bsums[t] = tmp[t] - v;
    } else {
        int v = g_gcnt[t];
        tmp[t] = v;
        __syncthreads();
        for (int off = 1; off < GG; off <<= 1) {
            int add = (t >= off) ? tmp[t - off] : 0;
            __syncthreads();
            tmp[t] += add;
            __syncthreads();
        }
        g_goff[t] = tmp[t] - v;
        if (t == GG - 1) g_goff[GG] = tmp[t];
    }
}
__global__ void k_scan3() {
    int t = threadIdx.x;
    int g = blockIdx.x * SCAN_B + t;
    if (g < NN) {
        int val = g_rowptr[g] + g_bsums[blockIdx.x];
        g_rowptr[g] = val;
        g_cursor[g] = val;
        if (g == 0) g_rowptr[NN] = EE;
    }
}
__global__ void k_fill(const int* __restrict__ src, const int* __restrict__ dst) {
    int i = blockIdx.x * blockDim.x + threadIdx.x;
    if (i >= EE / 4) return;
    int4 d = ((const int4*)dst)[i];
    int4 s = ((const int4*)src)[i];
    int p0 = atomicAdd(&g_cursor[d.x], 1);
    int p1 = atomicAdd(&g_cursor[d.y], 1);
    int p2 = atomicAdd(&g_cursor[d.z], 1);
    int p3 = atomicAdd(&g_cursor[d.w], 1);
    g_colidx[p0] = s.x;
    g_colidx[p1] = s.y;
    g_colidx[p2] = s.z;
    g_colidx[p3] = s.w;
}

// ---------------- merged prep: x->fp16 convert + weight split/transpose ----------------
#define XWORK (NN * DD / 4)
#define WWORK (7 * DD * DD)
__global__ void k_prep(const float* __restrict__ x,
                       const float* __restrict__ W1, const float* __restrict__ W2,
                       const float* __restrict__ linW) {
    int i = blockIdx.x * 256 + threadIdx.x;
    if (i < XWORK) {
        float4 v = ((const float4*)x)[i];
        __half2 a = __floats2half2_rn(v.x, v.y);
        __half2 b = __floats2half2_rn(v.z, v.w);
        ((uint2*)g_hx)[i] = make_uint2(*(uint32_t*)&a, *(uint32_t*)&b);
    } else {
        int j = i - XWORK;
        if (j < WWORK) {
            int m = j >> 14, r = j & 16383;
            int k = r >> 7, n = r & 127;
            const float* src = (m < 3) ? (W1 + m * DD * DD)
                                       : ((m < 6) ? (W2 + (m - 3) * DD * DD) : linW);
            float v = src[k * DD + n];
            __half h = __float2half_rn(v);
            g_wh[m * DD * DD + n * DD + k] = h;
            if (m == 6)
                g_wl[n * DD + k] = __float2half_rn(v - __half2float(h));
        }
    }
}

// ---------------- GIN aggregate: half-warp per row (LDG.128, 2 rows per warp-load) ----------------
__device__ __forceinline__ void acc_u4(float* acc, uint4 v) {
    float2 f0 = __half22float2(*(__half2*)&v.x);
    float2 f1 = __half22float2(*(__half2*)&v.y);
    float2 f2 = __half22float2(*(__half2*)&v.z);
    float2 f3 = __half22float2(*(__half2*)&v.w);
    acc[0] += f0.x; acc[1] += f0.y; acc[2] += f1.x; acc[3] += f1.y;
    acc[4] += f2.x; acc[5] += f2.y; acc[6] += f3.x; acc[7] += f3.y;
}

__global__ void k_agg(const float* __restrict__ eps, int layer,
                      const __half* __restrict__ hin, __half* __restrict__ aout) {
    int w = (blockIdx.x * blockDim.x + threadIdx.x) >> 5;
    if (w >= NN) return;
    int lane = threadIdx.x & 31;
    int half = lane >> 4, li = lane & 15;     // half-warp owns one row per step
    const uint4* hp = (const uint4*)hin;      // 16 uint4 per 128-col row
    float acc[8];
#pragma unroll
    for (int r = 0; r < 8; r++) acc[r] = 0.f;

    int s = g_rowptr[w], e = g_rowptr[w + 1];
    int j = s + half;                          // half 0: even offsets, half 1: odd
    // unrolled: 4 neighbors per half per iter (MLP 4)
    for (; j + 6 < e; j += 8) {
        int n0 = g_colidx[j], n1 = g_colidx[j + 2], n2 = g_colidx[j + 4], n3 = g_colidx[j + 6];
        uint4 v0 = hp[(size_t)n0 * 16 + li];
        uint4 v1 = hp[(size_t)n1 * 16 + li];
        uint4 v2 = hp[(size_t)n2 * 16 + li];
        uint4 v3 = hp[(size_t)n3 * 16 + li];
        acc_u4(acc, v0);
        acc_u4(acc, v1);
        acc_u4(acc, v2);
        acc_u4(acc, v3);
    }
    for (; j < e; j += 2) {
        int n0 = g_colidx[j];
        uint4 v = hp[(size_t)n0 * 16 + li];
        acc_u4(acc, v);
    }

    // combine halves: lanes l and l^16 hold the same 8 columns
#pragma unroll
    for (int r = 0; r < 8; r++) acc[r] += __shfl_xor_sync(0xffffffff, acc[r], 16);

    // half 0 adds (1+eps)*self and writes the output row
    if (half == 0) {
        float epsv = 1.0f + __ldg(&eps[layer]);
        uint4 sv = hp[(size_t)w * 16 + li];
        float2 f0 = __half22float2(*(__half2*)&sv.x);
        float2 f1 = __half22float2(*(__half2*)&sv.y);
        float2 f2 = __half22float2(*(__half2*)&sv.z);
        float2 f3 = __half22float2(*(__half2*)&sv.w);
        acc[0] += epsv * f0.x; acc[1] += epsv * f0.y;
        acc[2] += epsv * f1.x; acc[3] += epsv * f1.y;
        acc[4] += epsv * f2.x; acc[5] += epsv * f2.y;
        acc[6] += epsv * f3.x; acc[7] += epsv * f3.y;
        __half2 p0 = __floats2half2_rn(acc[0], acc[1]);
        __half2 p1 = __floats2half2_rn(acc[2], acc[3]);
        __half2 p2 = __floats2half2_rn(acc[4], acc[5]);
        __half2 p3 = __floats2half2_rn(acc[6], acc[7]);
        uint4 o;
        o.x = *(uint32_t*)&p0; o.y = *(uint32_t*)&p1;
        o.z = *(uint32_t*)&p2; o.w = *(uint32_t*)&p3;
        ((uint4*)aout)[(size_t)w * 16 + li] = o;
    }
}

// ---------------- GEMM tile cores ----------------
#define ROWB 272
#define BUFB (128 * ROWB)

// 16-warp core: warp tile 32x32 (k_layer, 512 threads), single-product
__device__ __forceinline__ void gemm_tile16(uint32_t sb, uint32_t smA, uint32_t smW,
                                            int wid, int lane, float acc[2][4][4]) {
    int warp_m = wid & 3;
    int warp_n = wid >> 2;
    int q = lane >> 3, l7 = lane & 7;
    uint32_t a_row = (uint32_t)(warp_m * 32 + (q & 1) * 8 + l7);
    uint32_t a_cb  = (uint32_t)((q >> 1) * 16);
    uint32_t b_row = (uint32_t)(warp_n * 32 + (q >> 1) * 8 + l7);
    uint32_t b_cb  = (uint32_t)((q & 1) * 16);
#pragma unroll
    for (int ks = 0; ks < 8; ks++) {
        uint32_t kb = ks * 32;
        uint32_t ah[2][4], bh[4][2];
#pragma unroll
        for (int mi = 0; mi < 2; mi++)
            ldsm_x4(ah[mi], sb + smA + (a_row + mi * 16) * ROWB + kb + a_cb);
#pragma unroll
        for (int p = 0; p < 2; p++) {
            uint32_t off = (b_row + p * 16) * ROWB + kb + b_cb;
            uint32_t th[4];
            ldsm_x4(th, sb + smW + off);
            bh[p * 2][0] = th[0]; bh[p * 2][1] = th[1];
            bh[p * 2 + 1][0] = th[2]; bh[p * 2 + 1][1] = th[3];
        }
#pragma unroll
        for (int mi = 0; mi < 2; mi++)
#pragma unroll
            for (int ni = 0; ni < 4; ni++)
                mma16816h(acc[mi][ni], ah[mi], bh[ni]);
    }
}

// 8-warp core: warp tile 64x32 (k_lin, 256 threads), 2-product
__device__ __forceinline__ void gemm_tile8(uint32_t sb, uint32_t smA, uint32_t smWh, uint32_t smWl,
                                           int wid, int lane, float acc[4][4][4]) {
    int warp_m = wid & 1;
    int warp_n = wid >> 1;
    int q = lane >> 3, l7 = lane & 7;
    uint32_t a_row = (uint32_t)(warp_m * 64 + (q & 1) * 8 + l7);
    uint32_t a_cb  = (uint32_t)((q >> 1) * 16);
    uint32_t b_row = (uint32_t)(warp_n * 32 + (q >> 1) * 8 + l7);
    uint32_t b_cb  = (uint32_t)((q & 1) * 16);
#pragma unroll
    for (int ks = 0; ks < 8; ks++) {
        uint32_t kb = ks * 32;
        uint32_t ah[4][4], bh[4][2], bl[4][2];
#pragma unroll
        for (int mi = 0; mi < 4; mi++)
            ldsm_x4(ah[mi], sb + smA + (a_row + mi * 16) * ROWB + kb + a_cb);
#pragma unroll
        for (int p = 0; p < 2; p++) {
            uint32_t off = (b_row + p * 16) * ROWB + kb + b_cb;
            uint32_t th[4], tl[4];
            ldsm_x4(th, sb + smWh + off);
            ldsm_x4(tl, sb + smWl + off);
            bh[p * 2][0] = th[0]; bh[p * 2][1] = th[1];
            bh[p * 2 + 1][0] = th[2]; bh[p * 2 + 1][1] = th[3];
            bl[p * 2][0] = tl[0]; bl[p * 2][1] = tl[1];
            bl[p * 2 + 1][0] = tl[2]; bl[p * 2 + 1][1] = tl[3];
        }
#pragma unroll
        for (int mi = 0; mi < 4; mi++)
#pragma unroll
            for (int ni = 0; ni < 4; ni++) {
                mma16816h(acc[mi][ni], ah[mi], bh[ni]);
                mma16816h(acc[mi][ni], ah[mi], bl[ni]);
            }
    }
}

// ---------------- persistent fused layer (512 threads), cp.async double-buffered A ----------------
#define SM_A0  1536
#define SM_A1  (SM_A0 + BUFB)
#define SM_Z   (SM_A1 + BUFB)
#define SM_W1H (SM_Z + BUFB)
#define SM_W2H (SM_W1H + BUFB)
#define SMEM_F (SM_W2H + BUFB)    // 175616

__global__ void __launch_bounds__(512, 1)
k_layer(const __half* __restrict__ A, __half* __restrict__ hout,
        const __half* __restrict__ W1h, const __half* __restrict__ W2h,
        const float* __restrict__ b1, const float* __restrict__ b2,
        const float* __restrict__ gamma, const float* __restrict__ beta,
        const float* __restrict__ rmean, const float* __restrict__ rvar, int M) {
    extern __shared__ char smem[];
    uint32_t sb = smem_u32(smem);
    int tid = threadIdx.x;
    int wid = tid >> 5;
    int lane = tid & 31;

    float* s_b1 = (float*)(smem + 0);
    float* s_b2 = (float*)(smem + 512);
    float* s_sc = (float*)(smem + 1024);

    if (tid < 128) {
        s_b1[tid] = b1[tid];
        s_b2[tid] = b2[tid];
        float inv = rsqrtf(rvar[tid] + 1e-5f);
        s_sc[tid] = gamma[tid] * inv;
    }

    for (int c = tid; c < 2048; c += 512) {
        int row = c >> 4, kc = c & 15;
        uint32_t off = (uint32_t)(row * ROWB + kc * 16);
        size_t woff = (size_t)row * DD + kc * 8;
        *(uint4*)(smem + SM_W1H + off) = *(const uint4*)(W1h + woff);
        *(uint4*)(smem + SM_W2H + off) = *(const uint4*)(W2h + woff);
    }

    int warp_m = wid & 3, warp_n = wid >> 2;
    int l4 = lane >> 2, lm = lane & 3;
    int ntiles = (M + 127) / 128;
    int stride = gridDim.x;

    auto stageA = [&](int t, uint32_t smA) {
        int base = t * 128;
#pragma unroll
        for (int it = 0; it < 4; it++) {
            int c = tid + it * 512;
            int row = c >> 4, kc = c & 15;
            uint32_t off = smA + (uint32_t)(row * ROWB + kc * 16);
            int grow = base + row;
            cp_async16(sb + off, A + (size_t)grow * DD + kc * 8, (grow < M) ? 16 : 0);
        }
    };

    int t = blockIdx.x;
    if (t < ntiles) stageA(t, SM_A0);
    CP_COMMIT();

    int buf = 0;
    for (; t < ntiles; t += stride, buf ^= 1) {
        int tn = t + stride;
        if (tn < ntiles) stageA(tn, buf ? SM_A0 : SM_A1);
        CP_COMMIT();
        CP_WAIT1();
        __syncthreads();

        uint32_t smA = buf ? SM_A1 : SM_A0;
        int base = t * 128;

        float acc[2][4][4];
#pragma unroll
        for (int mi = 0; mi < 2; mi++)
#pragma unroll
            for (int ni = 0; ni < 4; ni++)
#pragma unroll
                for (int r = 0; r < 4; r++) acc[mi][ni][r] = 0.f;

        gemm_tile16(sb, smA, SM_W1H, wid, lane, acc);

#pragma unroll
        for (int mi = 0; mi < 2; mi++) {
            int rloc = warp_m * 32 + mi * 16 + l4;
#pragma unroll
            for (int ni = 0; ni < 4; ni++) {
                int c0 = warp_n * 32 + ni * 8 + lm * 2;
                float bb0 = s_b1[c0], bb1 = s_b1[c0 + 1];
#pragma unroll
                for (int half = 0; half < 2; half++) {
                    float v0 = fmaxf(acc[mi][ni][half * 2] + bb0, 0.f);
                    float v1 = fmaxf(acc[mi][ni][half * 2 + 1] + bb1, 0.f);
                    __half2 z2 = __floats2half2_rn(v0, v1);
                    *(__half2*)(smem + SM_Z + (rloc + half * 8) * ROWB + c0 * 2) = z2;
                }
            }
        }
        __syncthreads();

#pragma unroll
        for (int mi = 0; mi < 2; mi++)
#pragma unroll
            for (int ni = 0; ni < 4; ni++)
#pragma unroll
                for (int r = 0; r < 4; r++) acc[mi][ni][r] = 0.f;

        gemm_tile16(sb, SM_Z, SM_W2H, wid, lane, acc);

#pragma unroll
        for (int mi = 0; mi < 2; mi++) {
            int r0 = base + warp_m * 32 + mi * 16 + l4;
#pragma unroll
            for (int ni = 0; ni < 4; ni++) {
                int c0 = warp_n * 32 + ni * 8 + lm * 2;
                float bb0 = s_b2[c0], bb1 = s_b2[c0 + 1];
                float sc0 = s_sc[c0], sc1 = s_sc[c0 + 1];
                float sh0 = beta[c0] - rmean[c0] * sc0;
                float sh1 = beta[c0 + 1] - rmean[c0 + 1] * sc1;
#pragma unroll
                for (int half = 0; half < 2; half++) {
                    int row = r0 + half * 8;
                    if (row < M) {
                        float v0 = fmaxf(acc[mi][ni][half * 2] + bb0, 0.f) * sc0 + sh0;
                        float v1 = fmaxf(acc[mi][ni][half * 2 + 1] + bb1, 0.f) * sc1 + sh1;
                        __half2 x2 = __floats2half2_rn(v0, v1);
                        *(__half2*)(hout + (size_t)row * DD + c0) = x2;
                    }
                }
            }
        }
    }
}

// ---------------- lin1 kernel: out = relu(pooled @ W + b), fp32 out, 2-product ----------------
#define SM_A   1536
#define SM_LWH (SM_A + BUFB)
#define SM_LWL (SM_LWH + BUFB)
#define SMEM_L (SM_LWL + BUFB)

__global__ void __launch_bounds__(256, 1)
k_lin(const __half* __restrict__ Wh, const __half* __restrict__ Wl,
      const float* __restrict__ bias, float* __restrict__ out, int M) {
    extern __shared__ char smem[];
    uint32_t sb = smem_u32(smem);
    int tid = threadIdx.x;
    int wid = tid >> 5;
    int lane = tid & 31;
    int base = blockIdx.x * 128;

    float* s_bias = (float*)(smem + 0);
    if (tid < 128) s_bias[tid] = bias[tid];

    for (int c = tid; c < 2048; c += 256) {
        int row = c >> 4, kc = c & 15;
        uint32_t off = (uint32_t)(row * ROWB + kc * 16);
        int grow = base + row;
        uint4 va = make_uint4(0, 0, 0, 0);
        if (grow < M) va = *(const uint4*)(g_pf + (size_t)grow * DD + kc * 8);
        *(uint4*)(smem + SM_A + off) = va;
        size_t woff = (size_t)row * DD + kc * 8;
        *(uint4*)(smem + SM_LWH + off) = *(const uint4*)(Wh + woff);
        *(uint4*)(smem + SM_LWL + off) = *(const uint4*)(Wl + woff);
    }
    __syncthreads();

    float acc[4][4][4];
#pragma unroll
    for (int mi = 0; mi < 4; mi++)
#pragma unroll
        for (int ni = 0; ni < 4; ni++)
#pragma unroll
            for (int r = 0; r < 4; r++) acc[mi][ni][r] = 0.f;

    gemm_tile8(sb, SM_A, SM_LWH, SM_LWL, wid, lane, acc);

    int warp_m = wid & 1, warp_n = wid >> 1;
    int l4 = lane >> 2, lm = lane & 3;
#pragma unroll
    for (int mi = 0; mi < 4; mi++) {
        int r0 = base + warp_m * 64 + mi * 16 + l4;
#pragma unroll
        for (int ni = 0; ni < 4; ni++) {
            int c0 = warp_n * 32 + ni * 8 + lm * 2;
            float bb0 = s_bias[c0], bb1 = s_bias[c0 + 1];
#pragma unroll
            for (int half = 0; half < 2; half++) {
                int row = r0 + half * 8;
                if (row < M) {
                    float v0 = fmaxf(acc[mi][ni][half * 2] + bb0, 0.f);
                    float v1 = fmaxf(acc[mi][ni][half * 2 + 1] + bb1, 0.f);
                    *(float2*)(out + (size_t)row * DD + c0) = make_float2(v0, v1);
                }
            }
        }
    }
}

// ---------------- global mean pool (fp16 in -> fp16 out) ----------------
__global__ void k_pool(const __half* __restrict__ h) {
    int g = blockIdx.x;
    int t = threadIdx.x;
    int s = g_goff[g], e = g_goff[g + 1];
    float a0 = 0.f, a1 = 0.f, a2 = 0.f, a3 = 0.f;
    int i = s;
    for (; i + 3 < e; i += 4) {
        a0 += __half2float(h[(size_t)(i + 0) * DD + t]);
        a1 += __half2float(h[(size_t)(i + 1) * DD + t]);
        a2 += __half2float(h[(size_t)(i + 2) * DD + t]);
        a3 += __half2float(h[(size_t)(i + 3) * DD + t]);
    }
    for (; i < e; i++) a0 += __half2float(h[(size_t)i * DD + t]);
    float cnt = (float)((e - s) > 0 ? (e - s) : 1);
    g_pf[g * DD + t] = __float2half_rn((a0 + a1 + a2 + a3) / cnt);
}

// ---------------- launch (two-stream: prep || CSR, single join) ----------------
static cudaStream_t s2 = nullptr;
static cudaEvent_t evRoot, evPrep;

extern "C" void kernel_launch(void* const* d_in, const int* in_sizes, int n_in,
                              void* d_out, int out_size) {
    const float* x     = (const float*)d_in[0];
    const int*   ei    = (const int*)d_in[1];
    const int*   batch = (const int*)d_in[2];
    const float* W1    = (const float*)d_in[3];
    const float* b1    = (const float*)d_in[4];
    const float* W2    = (const float*)d_in[5];
    const float* b2    = (const float*)d_in[6];
    const float* gamma = (const float*)d_in[7];
    const float* beta  = (const float*)d_in[8];
    const float* rmean = (const float*)d_in[9];
    const float* rvar  = (const float*)d_in[10];
    const float* eps   = (const float*)d_in[11];
    const float* linW  = (const float*)d_in[12];
    const float* linb  = (const float*)d_in[13];
    float* out = (float*)d_out;

    const int* src = ei;
    const int* dst = ei + EE;

    __half *phx, *paf, *pwh, *pwl;
    void *pdeg, *pgcnt;
    cudaGetSymbolAddress((void**)&phx, g_hx);
    cudaGetSymbolAddress((void**)&paf, g_af);
    cudaGetSymbolAddress((void**)&pwh, g_wh);
    cudaGetSymbolAddress((void**)&pwl, g_wl);
    cudaGetSymbolAddress(&pdeg, g_deg);
    cudaGetSymbolAddress(&pgcnt, g_gcnt);

    if (s2 == nullptr) {
        cudaStreamCreateWithFlags(&s2, cudaStreamNonBlocking);
        cudaEventCreateWithFlags(&evRoot, cudaEventDisableTiming);
        cudaEventCreateWithFlags(&evPrep, cudaEventDisableTiming);
        cudaFuncSetAttribute(k_layer, cudaFuncAttributeMaxDynamicSharedMemorySize, SMEM_F);
        cudaFuncSetAttribute(k_lin,   cudaFuncAttributeMaxDynamicSharedMemorySize, SMEM_L);
    }

    // fork: prep on s2 runs concurrently with CSR build on stream 0
    cudaMemsetAsync(pdeg, 0, NN * sizeof(int));
    cudaMemsetAsync(pgcnt, 0, GG * sizeof(int));
    cudaEventRecord(evRoot, 0);
    cudaStreamWaitEvent(s2, evRoot, 0);
    k_prep<<<(XWORK + WWORK + 255) / 256, 256, 0, s2>>>(x, W1, W2, linW);
    cudaEventRecord(evPrep, s2);

    k_counts<<<(EE / 4 + 255) / 256, 256>>>(dst, batch);
    int nb = (NN + SCAN_B - 1) / SCAN_B;
    k_scan1<<<nb, SCAN_B>>>();
    k_scan2g<<<2, 512>>>(nb);
    k_scan3<<<nb, SCAN_B>>>();
    k_fill<<<(EE / 4 + 255) / 256, 256>>>(src, dst);

    // join: layers need g_hx and g_wh from prep
    cudaStreamWaitEvent(0, evPrep, 0);

    for (int l = 0; l < LL; l++) {
        k_agg<<<NN / 8, 256>>>(eps, l, phx, paf);
        k_layer<<<NSM, 512, SMEM_F>>>(paf, phx,
                pwh + l * DD * DD, pwh + (3 + l) * DD * DD,
                b1 + l * DD, b2 + l * DD,
                gamma + l * DD, beta + l * DD, rmean + l * DD, rvar + l * DD, NN);
    }

    k_pool<<<GG, DD>>>(phx);
    k_lin<<<(GG + 127) / 128, 256, SMEM_L>>>(pwh + 6 * DD * DD, pwl,
                                             linb, out, GG);
}

// round 16
// speedup vs baseline: 1.0702x; 1.0702x over previous
#include <cuda_runtime.h>
#include <cuda_fp16.h>
#include <cstdint>

#define NN 100000
#define EE 1600000
#define DD 128
#define LL 3
#define GG 512
#define NSM 148

// ---------------- scratch (device globals; no allocation allowed) ----------------
__device__ __half g_hx[NN * DD];        // h (and x): agg gather source / layer output
__device__ __half g_af[NN * DD];        // agg output (layer GEMM A operand)
__device__ __half g_wh[7 * DD * DD];    // weights hi (fp16), transposed [n][k]
__device__ __half g_wl[DD * DD];        // lin weight lo residual only
__device__ __half g_pf[GG * DD];        // pooled (fp16)
__device__ int   g_deg[NN];
__device__ int   g_rowptr[NN + 1];
__device__ int   g_cursor[NN];
__device__ int   g_colidx[EE];
__device__ int   g_bsums[512];
__device__ int   g_gcnt[GG];
__device__ int   g_goff[GG + 1];

// ---------------- PTX helpers ----------------
__device__ __forceinline__ uint32_t smem_u32(const void* p) {
    uint32_t a;
    asm("{ .reg .u64 t; cvta.to.shared.u64 t, %1; cvt.u32.u64 %0, t; }" : "=r"(a) : "l"(p));
    return a;
}
__device__ __forceinline__ void ldsm_x4(uint32_t* r, uint32_t addr) {
    asm volatile("ldmatrix.sync.aligned.m8n8.x4.shared.b16 {%0,%1,%2,%3}, [%4];"
        : "=r"(r[0]), "=r"(r[1]), "=r"(r[2]), "=r"(r[3]) : "r"(addr));
}
__device__ __forceinline__ void mma16816h(float* c, const uint32_t* a, const uint32_t* b) {
    asm volatile("mma.sync.aligned.m16n8k16.row.col.f32.f16.f16.f32 "
        "{%0,%1,%2,%3}, {%4,%5,%6,%7}, {%8,%9}, {%0,%1,%2,%3};"
        : "+f"(c[0]), "+f"(c[1]), "+f"(c[2]), "+f"(c[3])
        : "r"(a[0]), "r"(a[1]), "r"(a[2]), "r"(a[3]), "r"(b[0]), "r"(b[1]));
}
__device__ __forceinline__ void cp_async16(uint32_t smem_addr, const void* gptr, int src_bytes) {
    asm volatile("cp.async.cg.shared.global [%0], [%1], 16, %2;"
        :: "r"(smem_addr), "l"(gptr), "r"(src_bytes) : "memory");
}
#define CP_COMMIT() asm volatile("cp.async.commit_group;" ::: "memory")
#define CP_WAIT1()  asm volatile("cp.async.wait_group 1;" ::: "memory")

// ---------------- CSR + pool-offset build (vectorized) ----------------
__global__ void k_counts(const int* __restrict__ dst, const int* __restrict__ batch) {
    int i = blockIdx.x * blockDim.x + threadIdx.x;
    if (i < EE / 4) {
        int4 d = ((const int4*)dst)[i];
        atomicAdd(&g_deg[d.x], 1);
        atomicAdd(&g_deg[d.y], 1);
        atomicAdd(&g_deg[d.z], 1);
        atomicAdd(&g_deg[d.w], 1);
    }
    if (i < NN / 4) {
        int4 b = ((const int4*)batch)[i];
        atomicAdd(&g_gcnt[b.x], 1);
        atomicAdd(&g_gcnt[b.y], 1);
        atomicAdd(&g_gcnt[b.z], 1);
        atomicAdd(&g_gcnt[b.w], 1);
    }
}
#define SCAN_B 512
__global__ void k_scan1() {
    __shared__ int tmp[SCAN_B];
    int t = threadIdx.x;
    int g = blockIdx.x * SCAN_B + t;
    int v = (g < NN) ? g_deg[g] : 0;
    tmp[t] = v;
    __syncthreads();
    for (int off = 1; off < SCAN_B; off <<= 1) {
        int add = (t >= off) ? tmp[t - off] : 0;
        __syncthreads();
        tmp[t] += add;
        __syncthreads();
    }
    if (g < NN) g_rowptr[g] = tmp[t] - v;
    if (t == SCAN_B - 1) g_bsums[blockIdx.x] = tmp[t];
}
__global__ void k_scan2g(int nb) {
    __shared__ int tmp[512];
    int t = threadIdx.x;
    if (blockIdx.x == 0) {
        int v = (t < nb) ? g_bsums[t] : 0;
        tmp[t] = v;
        __syncthreads();
        for (int off = 1; off < 512; off <<= 1) {
            int add = (t >= off) ? tmp[t - off] : 0;
            __syncthreads();
            tmp[t] += add;
            __syncthreads();
        }
        if (t < nb) g_bsums[t] = tmp[t] - v;
    } else {
        int v = g_gcnt[t];
        tmp[t] = v;
        __syncthreads();
        for (int off = 1; off < GG; off <<= 1) {
            int add = (t >= off) ? tmp[t - off] : 0;
            __syncthreads();
            tmp[t] += add;
            __syncthreads();
        }
        g_goff[t] = tmp[t] - v;
        if (t == GG - 1) g_goff[GG] = tmp[t];
    }
}
__global__ void k_scan3() {
    int t = threadIdx.x;
    int g = blockIdx.x * SCAN_B + t;
    if (g < NN) {
        int val = g_rowptr[g] + g_bsums[blockIdx.x];
        g_rowptr[g] = val;
        g_cursor[g] = val;
        if (g == 0) g_rowptr[NN] = EE;
    }
}
__global__ void k_fill(const int* __restrict__ src, const int* __restrict__ dst) {
    int i = blockIdx.x * blockDim.x + threadIdx.x;
    if (i >= EE / 4) return;
    int4 d = ((const int4*)dst)[i];
    int4 s = ((const int4*)src)[i];
    int p0 = atomicAdd(&g_cursor[d.x], 1);
    int p1 = atomicAdd(&g_cursor[d.y], 1);
    int p2 = atomicAdd(&g_cursor[d.z], 1);
    int p3 = atomicAdd(&g_cursor[d.w], 1);
    g_colidx[p0] = s.x;
    g_colidx[p1] = s.y;
    g_colidx[p2] = s.z;
    g_colidx[p3] = s.w;
}

// ---------------- merged prep: x->fp16 convert + weight split/transpose ----------------
#define XWORK (NN * DD / 4)
#define WWORK (7 * DD * DD)
__global__ void k_prep(const float* __restrict__ x,
                       const float* __restrict__ W1, const float* __restrict__ W2,
                       const float* __restrict__ linW) {
    int i = blockIdx.x * 256 + threadIdx.x;
    if (i < XWORK) {
        float4 v = ((const float4*)x)[i];
        __half2 a = __floats2half2_rn(v.x, v.y);
        __half2 b = __floats2half2_rn(v.z, v.w);
        ((uint2*)g_hx)[i] = make_uint2(*(uint32_t*)&a, *(uint32_t*)&b);
    } else {
        int j = i - XWORK;
        if (j < WWORK) {
            int m = j >> 14, r = j & 16383;
            int k = r >> 7, n = r & 127;
            const float* src = (m < 3) ? (W1 + m * DD * DD)
                                       : ((m < 6) ? (W2 + (m - 3) * DD * DD) : linW);
            float v = src[k * DD + n];
            __half h = __float2half_rn(v);
            g_wh[m * DD * DD + n * DD + k] = h;
            if (m == 6)
                g_wl[n * DD + k] = __float2half_rn(v - __half2float(h));
        }
    }
}

// ---------------- GIN aggregate + combine (fp16 gather -> fp16 out) ----------------
__global__ void k_agg(const float* __restrict__ eps, int layer,
                      const __half* __restrict__ hin, __half* __restrict__ aout) {
    int w = (blockIdx.x * blockDim.x + threadIdx.x) >> 5;
    if (w >= NN) return;
    int lane = threadIdx.x & 31;
    float epsv = 1.0f + __ldg(&eps[layer]);
    const uint2* hp = (const uint2*)hin;
    uint2 sv = hp[(size_t)w * 32 + lane];
    float2 s01 = __half22float2(*(__half2*)&sv.x);
    float2 s23 = __half22float2(*(__half2*)&sv.y);
    float ax = s01.x * epsv, ay = s01.y * epsv, az = s23.x * epsv, aw = s23.y * epsv;
    int s = g_rowptr[w], e = g_rowptr[w + 1];
    int j = s;
    for (; j + 3 < e; j += 4) {
        int s0 = g_colidx[j], s1 = g_colidx[j + 1], s2 = g_colidx[j + 2], s3 = g_colidx[j + 3];
        uint2 v0 = hp[(size_t)s0 * 32 + lane];
        uint2 v1 = hp[(size_t)s1 * 32 + lane];
        uint2 v2 = hp[(size_t)s2 * 32 + lane];
        uint2 v3 = hp[(size_t)s3 * 32 + lane];
        float2 a0 = __half22float2(*(__half2*)&v0.x), b0 = __half22float2(*(__half2*)&v0.y);
        float2 a1 = __half22float2(*(__half2*)&v1.x), b1 = __half22float2(*(__half2*)&v1.y);
        float2 a2 = __half22float2(*(__half2*)&v2.x), b2 = __half22float2(*(__half2*)&v2.y);
        float2 a3 = __half22float2(*(__half2*)&v3.x), b3 = __half22float2(*(__half2*)&v3.y);
        ax += a0.x + a1.x + a2.x + a3.x;
        ay += a0.y + a1.y + a2.y + a3.y;
        az += b0.x + b1.x + b2.x + b3.x;
        aw += b0.y + b1.y + b2.y + b3.y;
    }
    for (; j < e; j++) {
        int s0 = g_colidx[j];
        uint2 v = hp[(size_t)s0 * 32 + lane];
        float2 a = __half22float2(*(__half2*)&v.x), b = __half22float2(*(__half2*)&v.y);
        ax += a.x; ay += a.y; az += b.x; aw += b.y;
    }
    __half2 p0 = __floats2half2_rn(ax, ay);
    __half2 p1 = __floats2half2_rn(az, aw);
    ((uint2*)aout)[(size_t)w * 32 + lane] = make_uint2(*(uint32_t*)&p0, *(uint32_t*)&p1);
}

// ---------------- GEMM tile cores ----------------
#define ROWB 272
#define BUFB (128 * ROWB)

// 16-warp core: warp tile 32x32 (k_layer, 512 threads), single-product
__device__ __forceinline__ void gemm_tile16(uint32_t sb, uint32_t smA, uint32_t smW,
                                            int wid, int lane, float acc[2][4][4]) {
    int warp_m = wid & 3;
    int warp_n = wid >> 2;
    int q = lane >> 3, l7 = lane & 7;
    uint32_t a_row = (uint32_t)(warp_m * 32 + (q & 1) * 8 + l7);
    uint32_t a_cb  = (uint32_t)((q >> 1) * 16);
    uint32_t b_row = (uint32_t)(warp_n * 32 + (q >> 1) * 8 + l7);
    uint32_t b_cb  = (uint32_t)((q & 1) * 16);
#pragma unroll
    for (int ks = 0; ks < 8; ks++) {
        uint32_t kb = ks * 32;
        uint32_t ah[2][4], bh[4][2];
#pragma unroll
        for (int mi = 0; mi < 2; mi++)
            ldsm_x4(ah[mi], sb + smA + (a_row + mi * 16) * ROWB + kb + a_cb);
#pragma unroll
        for (int p = 0; p < 2; p++) {
            uint32_t off = (b_row + p * 16) * ROWB + kb + b_cb;
            uint32_t th[4];
            ldsm_x4(th, sb + smW + off);
            bh[p * 2][0] = th[0]; bh[p * 2][1] = th[1];
            bh[p * 2 + 1][0] = th[2]; bh[p * 2 + 1][1] = th[3];
        }
#pragma unroll
        for (int mi = 0; mi < 2; mi++)
#pragma unroll
            for (int ni = 0; ni < 4; ni++)
                mma16816h(acc[mi][ni], ah[mi], bh[ni]);
    }
}

// 8-warp core: warp tile 64x32 (k_lin, 256 threads), 2-product
__device__ __forceinline__ void gemm_tile8(uint32_t sb, uint32_t smA, uint32_t smWh, uint32_t smWl,
                                           int wid, int lane, float acc[4][4][4]) {
    int warp_m = wid & 1;
    int warp_n = wid >> 1;
    int q = lane >> 3, l7 = lane & 7;
    uint32_t a_row = (uint32_t)(warp_m * 64 + (q & 1) * 8 + l7);
    uint32_t a_cb  = (uint32_t)((q >> 1) * 16);
    uint32_t b_row = (uint32_t)(warp_n * 32 + (q >> 1) * 8 + l7);
    uint32_t b_cb  = (uint32_t)((q & 1) * 16);
#pragma unroll
    for (int ks = 0; ks < 8; ks++) {
        uint32_t kb = ks * 32;
        uint32_t ah[4][4], bh[4][2], bl[4][2];
#pragma unroll
        for (int mi = 0; mi < 4; mi++)
            ldsm_x4(ah[mi], sb + smA + (a_row + mi * 16) * ROWB + kb + a_cb);
#pragma unroll
        for (int p = 0; p < 2; p++) {
            uint32_t off = (b_row + p * 16) * ROWB + kb + b_cb;
            uint32_t th[4], tl[4];
            ldsm_x4(th, sb + smWh + off);
            ldsm_x4(tl, sb + smWl + off);
            bh[p * 2][0] = th[0]; bh[p * 2][1] = th[1];
            bh[p * 2 + 1][0] = th[2]; bh[p * 2 + 1][1] = th[3];
            bl[p * 2][0] = tl[0]; bl[p * 2][1] = tl[1];
            bl[p * 2 + 1][0] = tl[2]; bl[p * 2 + 1][1] = tl[3];
        }
#pragma unroll
        for (int mi = 0; mi < 4; mi++)
#pragma unroll
            for (int ni = 0; ni < 4; ni++) {
                mma16816h(acc[mi][ni], ah[mi], bh[ni]);
                mma16816h(acc[mi][ni], ah[mi], bl[ni]);
            }
    }
}

// ---------------- persistent fused layer (512 threads), cp.async double-buffered A ----------------
#define SM_A0  1536
#define SM_A1  (SM_A0 + BUFB)
#define SM_Z   (SM_A1 + BUFB)
#define SM_W1H (SM_Z + BUFB)
#define SM_W2H (SM_W1H + BUFB)
#define SMEM_F (SM_W2H + BUFB)    // 175616

__global__ void __launch_bounds__(512, 1)
k_layer(const __half* __restrict__ A, __half* __restrict__ hout,
        const __half* __restrict__ W1h, const __half* __restrict__ W2h,
        const float* __restrict__ b1, const float* __restrict__ b2,
        const float* __restrict__ gamma, const float* __restrict__ beta,
        const float* __restrict__ rmean, const float* __restrict__ rvar, int M) {
    extern __shared__ char smem[];
    uint32_t sb = smem_u32(smem);
    int tid = threadIdx.x;
    int wid = tid >> 5;
    int lane = tid & 31;

    float* s_b1 = (float*)(smem + 0);
    float* s_b2 = (float*)(smem + 512);
    float* s_sc = (float*)(smem + 1024);

    if (tid < 128) {
        s_b1[tid] = b1[tid];
        s_b2[tid] = b2[tid];
        float inv = rsqrtf(rvar[tid] + 1e-5f);
        s_sc[tid] = gamma[tid] * inv;
    }

    for (int c = tid; c < 2048; c += 512) {
        int row = c >> 4, kc = c & 15;
        uint32_t off = (uint32_t)(row * ROWB + kc * 16);
        size_t woff = (size_t)row * DD + kc * 8;
        *(uint4*)(smem + SM_W1H + off) = *(const uint4*)(W1h + woff);
        *(uint4*)(smem + SM_W2H + off) = *(const uint4*)(W2h + woff);
    }

    int warp_m = wid & 3, warp_n = wid >> 2;
    int l4 = lane >> 2, lm = lane & 3;
    int ntiles = (M + 127) / 128;
    int stride = gridDim.x;

    auto stageA = [&](int t, uint32_t smA) {
        int base = t * 128;
#pragma unroll
        for (int it = 0; it < 4; it++) {
            int c = tid + it * 512;
            int row = c >> 4, kc = c & 15;
            uint32_t off = smA + (uint32_t)(row * ROWB + kc * 16);
            int grow = base + row;
            cp_async16(sb + off, A + (size_t)grow * DD + kc * 8, (grow < M) ? 16 : 0);
        }
    };

    int t = blockIdx.x;
    if (t < ntiles) stageA(t, SM_A0);
    CP_COMMIT();

    int buf = 0;
    for (; t < ntiles; t += stride, buf ^= 1) {
        int tn = t + stride;
        if (tn < ntiles) stageA(tn, buf ? SM_A0 : SM_A1);
        CP_COMMIT();
        CP_WAIT1();
        __syncthreads();

        uint32_t smA = buf ? SM_A1 : SM_A0;
        int base = t * 128;

        float acc[2][4][4];
#pragma unroll
        for (int mi = 0; mi < 2; mi++)
#pragma unroll
            for (int ni = 0; ni < 4; ni++)
#pragma unroll
                for (int r = 0; r < 4; r++) acc[mi][ni][r] = 0.f;

        gemm_tile16(sb, smA, SM_W1H, wid, lane, acc);

#pragma unroll
        for (int mi = 0; mi < 2; mi++) {
            int rloc = warp_m * 32 + mi * 16 + l4;
#pragma unroll
            for (int ni = 0; ni < 4; ni++) {
                int c0 = warp_n * 32 + ni * 8 + lm * 2;
                float bb0 = s_b1[c0], bb1 = s_b1[c0 + 1];
#pragma unroll
                for (int half = 0; half < 2; half++) {
                    float v0 = fmaxf(acc[mi][ni][half * 2] + bb0, 0.f);
                    float v1 = fmaxf(acc[mi][ni][half * 2 + 1] + bb1, 0.f);
                    __half2 z2 = __floats2half2_rn(v0, v1);
                    *(__half2*)(smem + SM_Z + (rloc + half * 8) * ROWB + c0 * 2) = z2;
                }
            }
        }
        __syncthreads();

#pragma unroll
        for (int mi = 0; mi < 2; mi++)
#pragma unroll
            for (int ni = 0; ni < 4; ni++)
#pragma unroll
                for (int r = 0; r < 4; r++) acc[mi][ni][r] = 0.f;

        gemm_tile16(sb, SM_Z, SM_W2H, wid, lane, acc);

#pragma unroll
        for (int mi = 0; mi < 2; mi++) {
            int r0 = base + warp_m * 32 + mi * 16 + l4;
#pragma unroll
            for (int ni = 0; ni < 4; ni++) {
                int c0 = warp_n * 32 + ni * 8 + lm * 2;
                float bb0 = s_b2[c0], bb1 = s_b2[c0 + 1];
                float sc0 = s_sc[c0], sc1 = s_sc[c0 + 1];
                float sh0 = beta[c0] - rmean[c0] * sc0;
                float sh1 = beta[c0 + 1] - rmean[c0 + 1] * sc1;
#pragma unroll
                for (int half = 0; half < 2; half++) {
                    int row = r0 + half * 8;
                    if (row < M) {
                        float v0 = fmaxf(acc[mi][ni][half * 2] + bb0, 0.f) * sc0 + sh0;
                        float v1 = fmaxf(acc[mi][ni][half * 2 + 1] + bb1, 0.f) * sc1 + sh1;
                        __half2 x2 = __floats2half2_rn(v0, v1);
                        *(__half2*)(hout + (size_t)row * DD + c0) = x2;
                    }
                }
            }
        }
    }
}

// ---------------- lin1 kernel: out = relu(pooled @ W + b), fp32 out, 2-product ----------------
#define SM_A   1536
#define SM_LWH (SM_A + BUFB)
#define SM_LWL (SM_LWH + BUFB)
#define SMEM_L (SM_LWL + BUFB)

__global__ void __launch_bounds__(256, 1)
k_lin(const __half* __restrict__ Wh, const __half* __restrict__ Wl,
      const float* __restrict__ bias, float* __restrict__ out, int M) {
    extern __shared__ char smem[];
    uint32_t sb = smem_u32(smem);
    int tid = threadIdx.x;
    int wid = tid >> 5;
    int lane = tid & 31;
    int base = blockIdx.x * 128;

    float* s_bias = (float*)(smem + 0);
    if (tid < 128) s_bias[tid] = bias[tid];

    for (int c = tid; c < 2048; c += 256) {
        int row = c >> 4, kc = c & 15;
        uint32_t off = (uint32_t)(row * ROWB + kc * 16);
        int grow = base + row;
        uint4 va = make_uint4(0, 0, 0, 0);
        if (grow < M) va = *(const uint4*)(g_pf + (size_t)grow * DD + kc * 8);
        *(uint4*)(smem + SM_A + off) = va;
        size_t woff = (size_t)row * DD + kc * 8;
        *(uint4*)(smem + SM_LWH + off) = *(const uint4*)(Wh + woff);
        *(uint4*)(smem + SM_LWL + off) = *(const uint4*)(Wl + woff);
    }
    __syncthreads();

    float acc[4][4][4];
#pragma unroll
    for (int mi = 0; mi < 4; mi++)
#pragma unroll
        for (int ni = 0; ni < 4; ni++)
#pragma unroll
            for (int r = 0; r < 4; r++) acc[mi][ni][r] = 0.f;

    gemm_tile8(sb, SM_A, SM_LWH, SM_LWL, wid, lane, acc);

    int warp_m = wid & 1, warp_n = wid >> 1;
    int l4 = lane >> 2, lm = lane & 3;
#pragma unroll
    for (int mi = 0; mi < 4; mi++) {
        int r0 = base + warp_m * 64 + mi * 16 + l4;
#pragma unroll
        for (int ni = 0; ni < 4; ni++) {
            int c0 = warp_n * 32 + ni * 8 + lm * 2;
            float bb0 = s_bias[c0], bb1 = s_bias[c0 + 1];
#pragma unroll
            for (int half = 0; half < 2; half++) {
                int row = r0 + half * 8;
                if (row < M) {
                    float v0 = fmaxf(acc[mi][ni][half * 2] + bb0, 0.f);
                    float v1 = fmaxf(acc[mi][ni][half * 2 + 1] + bb1, 0.f);
                    *(float2*)(out + (size_t)row * DD + c0) = make_float2(v0, v1);
                }
            }
        }
    }
}

// ---------------- global mean pool (fp16 in -> fp16 out) ----------------
__global__ void k_pool(const __half* __restrict__ h) {
    int g = blockIdx.x;
    int t = threadIdx.x;
    int s = g_goff[g], e = g_goff[g + 1];
    float a0 = 0.f, a1 = 0.f, a2 = 0.f, a3 = 0.f;
    int i = s;
    for (; i + 3 < e; i += 4) {
        a0 += __half2float(h[(size_t)(i + 0) * DD + t]);
        a1 += __half2float(h[(size_t)(i + 1) * DD + t]);
        a2 += __half2float(h[(size_t)(i + 2) * DD + t]);
        a3 += __half2float(h[(size_t)(i + 3) * DD + t]);
    }
    for (; i < e; i++) a0 += __half2float(h[(size_t)i * DD + t]);
    float cnt = (float)((e - s) > 0 ? (e - s) : 1);
    g_pf[g * DD + t] = __float2half_rn((a0 + a1 + a2 + a3) / cnt);
}

// ---------------- launch (two-stream: prep || CSR, single join) ----------------
static cudaStream_t s2 = nullptr;
static cudaEvent_t evRoot, evPrep;

extern "C" void kernel_launch(void* const* d_in, const int* in_sizes, int n_in,
                              void* d_out, int out_size) {
    const float* x     = (const float*)d_in[0];
    const int*   ei    = (const int*)d_in[1];
    const int*   batch = (const int*)d_in[2];
    const float* W1    = (const float*)d_in[3];
    const float* b1    = (const float*)d_in[4];
    const float* W2    = (const float*)d_in[5];
    const float* b2    = (const float*)d_in[6];
    const float* gamma = (const float*)d_in[7];
    const float* beta  = (const float*)d_in[8];
    const float* rmean = (const float*)d_in[9];
    const float* rvar  = (const float*)d_in[10];
    const float* eps   = (const float*)d_in[11];
    const float* linW  = (const float*)d_in[12];
    const float* linb  = (const float*)d_in[13];
    float* out = (float*)d_out;

    const int* src = ei;
    const int* dst = ei + EE;

    __half *phx, *paf, *pwh, *pwl;
    void *pdeg, *pgcnt;
    cudaGetSymbolAddress((void**)&phx, g_hx);
    cudaGetSymbolAddress((void**)&paf, g_af);
    cudaGetSymbolAddress((void**)&pwh, g_wh);
    cudaGetSymbolAddress((void**)&pwl, g_wl);
    cudaGetSymbolAddress(&pdeg, g_deg);
    cudaGetSymbolAddress(&pgcnt, g_gcnt);

    if (s2 == nullptr) {
        cudaStreamCreateWithFlags(&s2, cudaStreamNonBlocking);
        cudaEventCreateWithFlags(&evRoot, cudaEventDisableTiming);
        cudaEventCreateWithFlags(&evPrep, cudaEventDisableTiming);
        cudaFuncSetAttribute(k_layer, cudaFuncAttributeMaxDynamicSharedMemorySize, SMEM_F);
        cudaFuncSetAttribute(k_lin,   cudaFuncAttributeMaxDynamicSharedMemorySize, SMEM_L);
    }

    // fork: prep on s2 runs concurrently with CSR build on stream 0
    cudaMemsetAsync(pdeg, 0, NN * sizeof(int));
    cudaMemsetAsync(pgcnt, 0, GG * sizeof(int));
    cudaEventRecord(evRoot, 0);
    cudaStreamWaitEvent(s2, evRoot, 0);
    k_prep<<<(XWORK + WWORK + 255) / 256, 256, 0, s2>>>(x, W1, W2, linW);
    cudaEventRecord(evPrep, s2);

    k_counts<<<(EE / 4 + 255) / 256, 256>>>(dst, batch);
    int nb = (NN + SCAN_B - 1) / SCAN_B;
    k_scan1<<<nb, SCAN_B>>>();
    k_scan2g<<<2, 512>>>(nb);
    k_scan3<<<nb, SCAN_B>>>();
    k_fill<<<(EE / 4 + 255) / 256, 256>>>(src, dst);

    // join: layers need g_hx and g_wh from prep
    cudaStreamWaitEvent(0, evPrep, 0);

    for (int l = 0; l < LL; l++) {
        k_agg<<<NN / 8, 256>>>(eps, l, phx, paf);
        k_layer<<<NSM, 512, SMEM_F>>>(paf, phx,
                pwh + l * DD * DD, pwh + (3 + l) * DD * DD,
                b1 + l * DD, b2 + l * DD,
                gamma + l * DD, beta + l * DD, rmean + l * DD, rvar + l * DD, NN);
    }

    k_pool<<<GG, DD>>>(phx);
    k_lin<<<(GG + 127) / 128, 256, SMEM_L>>>(pwh + 6 * DD * DD, pwl,
                                             linb, out, GG);
}